// round 1
// baseline (speedup 1.0000x reference)
#include <cuda_runtime.h>
#include <math.h>

// Problem constants (fixed shapes from reference setup_inputs)
#define N_BATCH   64
#define C_IN      4
#define T_IN      300
#define V_IN      17
#define M_PERS    10
#define CF        256
#define TF        75
#define NUM_CLASS 60
#define KNN       4
#define LAMBDA_FUSE 0.1f
#define HIP_L 11
#define HIP_R 12

#define TV_COUNT (TF * V_IN)          // 1275
#define SLAB_F   (TV_COUNT * M_PERS)  // 12750 floats per (n,c)
#define SLAB_F2  (SLAB_F / 2)         // 6375 float2 per (n,c)

// Scratch (device globals: allocation-free)
__device__ float g_pf[N_BATCH * M_PERS * CF];   // pf[n][m][c]
__device__ float g_pos[N_BATCH * M_PERS * 3];   // pos[n][m][xyz]

// ----------------------------------------------------------------------------
// Kernel 1: pf[n][m][c] = mean over (t,v) of feat[n][c][t][v][m]
// One block per (n,c). 320 threads, float2 loads, fully coalesced.
// ----------------------------------------------------------------------------
__global__ __launch_bounds__(320) void k_pf_reduce(const float* __restrict__ feat) {
    const int b = blockIdx.x;            // n*CF + c
    const int n = b >> 8;                // /256
    const int c = b & 255;
    const int tid = threadIdx.x;

    const float2* __restrict__ slab =
        reinterpret_cast<const float2*>(feat + (size_t)b * SLAB_F);

    float s0 = 0.f, s1 = 0.f;
    // f = tid + 320*k ; f % 5 == tid % 5 (constant m-pair per thread)
#pragma unroll
    for (int k = 0; k < 20; k++) {
        int f = tid + 320 * k;
        if (f < SLAB_F2) {
            float2 v = slab[f];
            s0 += v.x;
            s1 += v.y;
        }
    }

    __shared__ float sm0[320];
    __shared__ float sm1[320];
    sm0[tid] = s0;
    sm1[tid] = s1;
    __syncthreads();

    if (tid < M_PERS) {
        const int m = tid;
        const int p = m >> 1;            // float2-pair slot within m-group (0..4)
        const float* src = (m & 1) ? sm1 : sm0;
        float acc = 0.f;
#pragma unroll
        for (int g = 0; g < 64; g++) acc += src[g * 5 + p];
        g_pf[(size_t)n * (M_PERS * CF) + m * CF + c] = acc * (1.0f / (float)TV_COUNT);
    }
}

// ----------------------------------------------------------------------------
// Kernel 2: pos[n][m][c] = mean_t 0.5*(x[n][c][t][11][m] + x[n][c][t][12][m])
// One block per (n, c<3). 320 threads: j in [0,20) covers v=11..12 x m=0..9.
// ----------------------------------------------------------------------------
__global__ __launch_bounds__(320) void k_pos_reduce(const float* __restrict__ x) {
    const int b = blockIdx.x;            // n*3 + c
    const int n = b / 3;
    const int c = b % 3;
    const int tid = threadIdx.x;
    const int j  = tid % 20;             // j<10: v=11,m=j ; j>=10: v=12,m=j-10
    const int tg = tid / 20;             // 0..15

    const float* base = x + ((size_t)(n * C_IN + c) * T_IN) * (V_IN * M_PERS);

    float s = 0.f;
#pragma unroll
    for (int k = 0; k < 19; k++) {
        int t = tg + 16 * k;
        if (t < T_IN) s += base[(size_t)t * (V_IN * M_PERS) + HIP_L * M_PERS + j];
    }

    __shared__ float red[320];
    __shared__ float s20[20];
    red[tid] = s;
    __syncthreads();

    if (tid < 20) {
        float acc = 0.f;
#pragma unroll
        for (int g = 0; g < 16; g++) acc += red[g * 20 + tid];
        s20[tid] = acc;
    }
    __syncthreads();

    if (tid < M_PERS) {
        float v = (s20[tid] + s20[tid + 10]) * 0.5f * (1.0f / (float)T_IN);
        g_pos[n * (M_PERS * 3) + tid * 3 + c] = v;
    }
}

// ----------------------------------------------------------------------------
// Kernel 3: per-sample head. One block per n, 256 threads.
//   h = pf @ Wp^T + bp ; A = knn adjacency ; h = relu(h + 0.1*A h)
//   hbar = mean_m h ; logits_tag = hbar @ Wc^T + bc
//   out = logits_base + sigmoid(tag_scale) * logits_tag
// ----------------------------------------------------------------------------
__global__ __launch_bounds__(256) void k_head(
    const float* __restrict__ logits_base,
    const float* __restrict__ proj_w, const float* __restrict__ proj_b,
    const float* __restrict__ cls_w,  const float* __restrict__ cls_b,
    const float* __restrict__ tag_scale,
    float* __restrict__ out)
{
    const int n   = blockIdx.x;
    const int tid = threadIdx.x;

    __shared__ float s_pf[M_PERS][CF];
    __shared__ float s_h [M_PERS][CF];
    __shared__ float s_A [M_PERS][M_PERS];
    __shared__ float s_d [M_PERS][M_PERS];
    __shared__ float s_pos[M_PERS][3];
    __shared__ float s_hbar[CF];

    // load pf slab and positions
    for (int i = tid; i < M_PERS * CF; i += 256) {
        s_pf[i >> 8][i & 255] = g_pf[(size_t)n * (M_PERS * CF) + i];
    }
    if (tid < M_PERS * 3) {
        s_pos[tid / 3][tid % 3] = g_pos[n * (M_PERS * 3) + tid];
    }
    __syncthreads();

    // ---- h = pf @ proj_w^T + proj_b : thread = output column c ----
    {
        const int c = tid;
        const float4* wrow = reinterpret_cast<const float4*>(proj_w + (size_t)c * CF);
        float acc[M_PERS];
#pragma unroll
        for (int m = 0; m < M_PERS; m++) acc[m] = 0.f;
#pragma unroll 4
        for (int kq = 0; kq < CF / 4; kq++) {
            float4 w4 = wrow[kq];
            int k = kq * 4;
#pragma unroll
            for (int m = 0; m < M_PERS; m++) {
                acc[m] += s_pf[m][k]     * w4.x;
                acc[m] += s_pf[m][k + 1] * w4.y;
                acc[m] += s_pf[m][k + 2] * w4.z;
                acc[m] += s_pf[m][k + 3] * w4.w;
            }
        }
        float bc = proj_b[c];
#pragma unroll
        for (int m = 0; m < M_PERS; m++) s_h[m][c] = acc[m] + bc;
    }

    // ---- pairwise distances ----
    if (tid < M_PERS * M_PERS) {
        int i = tid / M_PERS, j = tid % M_PERS;
        float dx = s_pos[i][0] - s_pos[j][0];
        float dy = s_pos[i][1] - s_pos[j][1];
        float dz = s_pos[i][2] - s_pos[j][2];
        s_d[i][j] = sqrtf(dx * dx + dy * dy + dz * dz);
    }
    __syncthreads();

    // ---- top-k (k=4 smallest, lowest-index tiebreak) + self loop + row norm ----
    if (tid < M_PERS) {
        const int i = tid;
        float a[M_PERS];
        bool sel[M_PERS];
#pragma unroll
        for (int j = 0; j < M_PERS; j++) { a[j] = 0.f; sel[j] = false; }
#pragma unroll
        for (int s = 0; s < KNN; s++) {
            int   arg  = -1;
            float best = 3.4e38f;
#pragma unroll
            for (int j = 0; j < M_PERS; j++) {
                if (!sel[j] && s_d[i][j] < best) { best = s_d[i][j]; arg = j; }
            }
            sel[arg] = true;
            a[arg] = 1.f;
        }
        a[i] += 1.f;   // self loop (eye)
        float rs = 0.f;
#pragma unroll
        for (int j = 0; j < M_PERS; j++) rs += a[j];
        float inv = 1.0f / (rs + 1e-6f);
#pragma unroll
        for (int j = 0; j < M_PERS; j++) s_A[i][j] = a[j] * inv;
    }
    __syncthreads();

    // ---- fuse + relu + mean over persons : thread = column c ----
    {
        const int c = tid;
        float hb = 0.f;
#pragma unroll
        for (int m = 0; m < M_PERS; m++) {
            float g = 0.f;
#pragma unroll
            for (int p = 0; p < M_PERS; p++) g += s_A[m][p] * s_h[p][c];
            float hf = s_h[m][c] + LAMBDA_FUSE * g;
            hf = fmaxf(hf, 0.f);
            hb += hf;
        }
        s_hbar[c] = hb * (1.0f / (float)M_PERS);
    }
    __syncthreads();

    // ---- classifier + gated add ----
    if (tid < NUM_CLASS) {
        const float4* wr = reinterpret_cast<const float4*>(cls_w + (size_t)tid * CF);
        float dot = 0.f;
#pragma unroll 4
        for (int kq = 0; kq < CF / 4; kq++) {
            float4 w4 = wr[kq];
            int k = kq * 4;
            dot += s_hbar[k]     * w4.x;
            dot += s_hbar[k + 1] * w4.y;
            dot += s_hbar[k + 2] * w4.z;
            dot += s_hbar[k + 3] * w4.w;
        }
        float lt   = dot + cls_b[tid];
        float gate = 1.0f / (1.0f + expf(-tag_scale[0]));   // * TAG_SCALE_MAX(1) * RAMP(1)
        out[n * NUM_CLASS + tid] = logits_base[n * NUM_CLASS + tid] + gate * lt;
    }
}

// ----------------------------------------------------------------------------
// Launch
// ----------------------------------------------------------------------------
extern "C" void kernel_launch(void* const* d_in, const int* in_sizes, int n_in,
                              void* d_out, int out_size) {
    const float* x           = (const float*)d_in[0];
    const float* feat        = (const float*)d_in[1];
    const float* logits_base = (const float*)d_in[2];
    const float* proj_w      = (const float*)d_in[3];
    const float* proj_b      = (const float*)d_in[4];
    const float* cls_w       = (const float*)d_in[5];
    const float* cls_b       = (const float*)d_in[6];
    const float* tag_scale   = (const float*)d_in[7];
    float* out = (float*)d_out;

    k_pf_reduce<<<N_BATCH * CF, 320>>>(feat);
    k_pos_reduce<<<N_BATCH * 3, 320>>>(x);
    k_head<<<N_BATCH, 256>>>(logits_base, proj_w, proj_b, cls_w, cls_b,
                             tag_scale, out);
}